// round 12
// baseline (speedup 1.0000x reference)
#include <cuda_runtime.h>
#include <cuda_fp16.h>
#include <cstdint>

// ImplicitFunction: fp16 m16n8k16 mma.sync, 2-term static weight split
// (W*s = Whi + Wlo), dynamically range-scaled fp16 activations.
// Round-12: r9 skeleton (32 rows/warp -> low per-point overhead) but with
// NT=384 (12 warps, 3 warps/SMSP, 1 CTA/SM) for +50% latency hiding at the
// same per-point alu/LDS cost. Weight-fragment cache shrunk to 4 uint4
// (two half-passes per k-tile, dep distance 8 preserved) to fit the
// 170-reg/thread budget at 384 threads. Cheap epilogue from r10/r11:
// s folded into weights, tree-max + redux.sync + rcp.approx.

#define NT 384
#define TILE_M 384          // 12 warps * 32 rows; 1 CTA/SM
#define NEG 0.2f
#define NLAYER 6

#define OFF_WF   0
#define WF_BYTES (NLAYER * 8 * 4 * 32 * 16)   // [l][nt][kt][lane]{hi0,hi1,lo0,lo1}
#define OFF_BH   (OFF_WF + WF_BYTES)
#define OFF_W0   (OFF_BH + 1536)
#define OFF_S0   (OFF_W0 + 768)
#define OFF_B0   (OFF_S0 + 256)
#define OFF_WO   (OFF_B0 + 256)
#define OFF_SOBO (OFF_WO + 256)
#define SMEM_BYTES (OFF_SOBO + 16)

__device__ __align__(16) uint32_t g_wfrag[NLAYER * 8 * 4 * 32 * 4];

static __device__ __forceinline__ float lrelu(float t) { return fmaxf(t, NEG * t); }

static __device__ __forceinline__ uint32_t pack_h2(float a, float b) {
    __half2 h = __floats2half2_rn(a, b);   // a -> low, b -> high
    return *(uint32_t*)&h;
}
static __device__ __forceinline__ float frcp(float x) {
    float r;
    asm("rcp.approx.f32 %0, %1;" : "=f"(r) : "f"(x));
    return r;
}
static __device__ __forceinline__ void mma_f16(float* c, const uint32_t* a,
                                               uint32_t b0, uint32_t b1) {
    asm volatile(
        "mma.sync.aligned.m16n8k16.row.col.f32.f16.f16.f32 "
        "{%0,%1,%2,%3}, {%4,%5,%6,%7}, {%8,%9}, {%0,%1,%2,%3};"
        : "+f"(c[0]), "+f"(c[1]), "+f"(c[2]), "+f"(c[3])
        : "r"(a[0]), "r"(a[1]), "r"(a[2]), "r"(a[3]), "r"(b0), "r"(b1));
}

// ---------------- prep: (W * diag(s)) -> fp16 hi/lo digits, B-fragment order ----------------
__global__ void prep_weights(const float* __restrict__ wh, const float* __restrict__ sh) {
    int t = blockIdx.x * blockDim.x + threadIdx.x;
    if (t >= NLAYER * 8 * 4 * 32) return;
    int lane = t & 31;
    int kt = (t >> 5) & 3;
    int nt = (t >> 7) & 7;
    int l = t >> 10;
    int k0 = kt * 16 + (lane & 3) * 2;
    int nn = nt * 8 + (lane >> 2);
    const float* W = wh + l * 4096;       // W[k][n] row-major
    float sv = sh[l * 64 + nn];
    float w0 = W[k0 * 64 + nn] * sv;
    float w1 = W[(k0 + 1) * 64 + nn] * sv;
    float w2 = W[(k0 + 8) * 64 + nn] * sv;
    float w3 = W[(k0 + 9) * 64 + nn] * sv;

    __half h0 = __float2half_rn(w0), h1 = __float2half_rn(w1);
    __half h2 = __float2half_rn(w2), h3 = __float2half_rn(w3);
    float l0 = w0 - __half2float(h0), l1 = w1 - __half2float(h1);
    float l2 = w2 - __half2float(h2), l3 = w3 - __half2float(h3);

    uint4 o;
    __half2 p01 = __halves2half2(h0, h1);
    __half2 p23 = __halves2half2(h2, h3);
    o.x = *(uint32_t*)&p01;
    o.y = *(uint32_t*)&p23;
    o.z = pack_h2(l0, l1);
    o.w = pack_h2(l2, l3);
    ((uint4*)g_wfrag)[t] = o;
}

// ---------------- device helpers ----------------
// quantize 32 post-activation values -> fp16 A fragments + per-rowhalf scales
static __device__ __forceinline__ void quantize_chain(
    const float (&o)[8][4], float& r0, float& r1,
    uint32_t (&A)[4][4], unsigned rmask)
{
    float p[8], q[8];
#pragma unroll
    for (int nt = 0; nt < 8; nt++) {
        p[nt] = fmaxf(fabsf(o[nt][0]), fabsf(o[nt][1]));
        q[nt] = fmaxf(fabsf(o[nt][2]), fabsf(o[nt][3]));
    }
    float m0 = fmaxf(fmaxf(fmaxf(p[0], p[1]), fmaxf(p[2], p[3])),
                     fmaxf(fmaxf(p[4], p[5]), fmaxf(p[6], p[7])));
    float m1 = fmaxf(fmaxf(fmaxf(q[0], q[1]), fmaxf(q[2], q[3])),
                     fmaxf(fmaxf(q[4], q[5]), fmaxf(q[6], q[7])));
    m0 = fmaxf(m0, 1e-30f);
    m1 = fmaxf(m1, 1e-30f);
    // positive fp32 bitpatterns are order-isomorphic to u32 -> REDUX over 4-lane group
    m0 = __uint_as_float(__reduce_max_sync(rmask, __float_as_uint(m0)));
    m1 = __uint_as_float(__reduce_max_sync(rmask, __float_as_uint(m1)));
    float inv0 = frcp(m0), inv1 = frcp(m1);
    r0 = m0;
    r1 = m1;
#pragma unroll
    for (int kt = 0; kt < 4; kt++) {
        A[kt][0] = pack_h2(o[2*kt][0]   * inv0, o[2*kt][1]   * inv0);
        A[kt][1] = pack_h2(o[2*kt][2]   * inv1, o[2*kt][3]   * inv1);
        A[kt][2] = pack_h2(o[2*kt+1][0] * inv0, o[2*kt+1][1] * inv0);
        A[kt][3] = pack_h2(o[2*kt+1][2] * inv1, o[2*kt+1][3] * inv1);
    }
}

// hidden-layer epilogue: dequant (s pre-folded into W) + bias + lrelu + quantize
static __device__ __forceinline__ void epi_full(
    const float (&acc)[8][4], float& r0, float& r1,
    const float* bl, int cb, uint32_t (&A)[4][4], unsigned rmask)
{
    const float R0 = r0, R1 = r1;
    float o[8][4];
#pragma unroll
    for (int nt = 0; nt < 8; nt++) {
        float2 bv = *(const float2*)(bl + nt * 8 + cb);
        o[nt][0] = lrelu(fmaf(acc[nt][0], R0, bv.x));
        o[nt][1] = lrelu(fmaf(acc[nt][1], R0, bv.y));
        o[nt][2] = lrelu(fmaf(acc[nt][2], R1, bv.x));
        o[nt][3] = lrelu(fmaf(acc[nt][3], R1, bv.y));
    }
    quantize_chain(o, r0, r1, A, rmask);
}

// one layer's MMA for both m-tiles: zero acc; per k-tile, two half-passes
// of 4 weight fragments each; hi then lo, dep distance 8 on each acc.
static __device__ __forceinline__ void mma_layer(
    const uint4* wl, const uint32_t (&A)[2][4][4], float (&acc)[2][8][4])
{
#pragma unroll
    for (int mt = 0; mt < 2; mt++)
#pragma unroll
        for (int nt = 0; nt < 8; nt++)
#pragma unroll
            for (int e = 0; e < 4; e++) acc[mt][nt][e] = 0.f;
#pragma unroll
    for (int kt = 0; kt < 4; kt++) {
#pragma unroll
        for (int half = 0; half < 2; half++) {
            uint4 wf[4];
#pragma unroll
            for (int q = 0; q < 4; q++)
                wf[q] = wl[(((half * 4 + q) * 4) + kt) * 32];
            // 8 independent hi-MMAs
#pragma unroll
            for (int q = 0; q < 4; q++) {
                mma_f16(acc[0][half * 4 + q], A[0][kt], wf[q].x, wf[q].y);
                mma_f16(acc[1][half * 4 + q], A[1][kt], wf[q].x, wf[q].y);
            }
            // 8 lo-MMAs (dep distance 8 back to the matching hi)
#pragma unroll
            for (int q = 0; q < 4; q++) {
                mma_f16(acc[0][half * 4 + q], A[0][kt], wf[q].z, wf[q].w);
                mma_f16(acc[1][half * 4 + q], A[1][kt], wf[q].z, wf[q].w);
            }
        }
    }
}

__global__ __launch_bounds__(NT, 1)
void implicit_mlp_f16(const float* __restrict__ points,
                      const float* __restrict__ w0,
                      const float* __restrict__ s0,
                      const float* __restrict__ b0,
                      const float* __restrict__ bh,
                      const float* __restrict__ wo,
                      const float* __restrict__ so,
                      const float* __restrict__ bo,
                      float* __restrict__ out,
                      int n, int ntiles)
{
    extern __shared__ __align__(16) unsigned char smem[];

    const int tid = threadIdx.x;
    const int wid = tid >> 5;
    const int lane = tid & 31;
    const int tig = lane & 3;
    const int grp = lane >> 2;
    const int cb = tig * 2;
    const unsigned rmask = 0xFu << (lane & ~3);

    {
        const uint4* gsrc = (const uint4*)g_wfrag;
        uint4* gdst = (uint4*)(smem + OFF_WF);
        for (int i = tid; i < WF_BYTES / 16; i += NT) gdst[i] = gsrc[i];
        float* d;
        d = (float*)(smem + OFF_BH); for (int i = tid; i < 384; i += NT) d[i] = bh[i];
        d = (float*)(smem + OFF_W0); for (int i = tid; i < 192; i += NT) d[i] = w0[i];
        d = (float*)(smem + OFF_S0); if (tid < 64) d[tid] = s0[tid];
        d = (float*)(smem + OFF_B0); if (tid < 64) d[tid] = b0[tid];
        d = (float*)(smem + OFF_WO); if (tid < 64) d[tid] = wo[tid];
        if (tid == 0) {
            ((float*)(smem + OFF_SOBO))[0] = so[0];
            ((float*)(smem + OFF_SOBO))[1] = bo[0];
        }
    }
    __syncthreads();

    const float* bh0    = (const float*)(smem + OFF_BH);
    const float* shm_w0 = (const float*)(smem + OFF_W0);
    const float* shm_s0 = (const float*)(smem + OFF_S0);
    const float* shm_b0 = (const float*)(smem + OFF_B0);
    const float* shm_wo = (const float*)(smem + OFF_WO);
    const float so_v = ((const float*)(smem + OFF_SOBO))[0];
    const float bo_v = ((const float*)(smem + OFF_SOBO))[1];
    const uint4* wfp = (const uint4*)(smem + OFF_WF) + lane;

    for (int tile = blockIdx.x; tile < ntiles; tile += gridDim.x) {
        const long long rowbase = (long long)tile * TILE_M + wid * 32;

        float acc[2][8][4];
        uint32_t A[2][4][4];
        float rm[2][2];

        // ---- layer 0 (K=3) scalar -> post-activation outputs in acc ----
#pragma unroll
        for (int mt = 0; mt < 2; mt++) {
            const long long r0 = rowbase + mt * 16 + grp;
            const long long r1 = r0 + 8;
            float ax = 0.f, ay = 0.f, az = 0.f, bx = 0.f, by = 0.f, bz = 0.f;
            if (r0 < n) { ax = points[r0*3+0]; ay = points[r0*3+1]; az = points[r0*3+2]; }
            if (r1 < n) { bx = points[r1*3+0]; by = points[r1*3+1]; bz = points[r1*3+2]; }
#pragma unroll
            for (int nt = 0; nt < 8; nt++) {
#pragma unroll
                for (int j = 0; j < 2; j++) {
                    int c = nt * 8 + cb + j;
                    float wa = shm_w0[c], wb = shm_w0[64 + c], wc = shm_w0[128 + c];
                    float sv = shm_s0[c], bv = shm_b0[c];
                    acc[mt][nt][j]     = lrelu(fmaf(fmaf(ax, wa, fmaf(ay, wb, az * wc)), sv, bv));
                    acc[mt][nt][2 + j] = lrelu(fmaf(fmaf(bx, wa, fmaf(by, wb, bz * wc)), sv, bv));
                }
            }
        }
        quantize_chain(acc[0], rm[0][0], rm[0][1], A[0], rmask);
        quantize_chain(acc[1], rm[1][0], rm[1][1], A[1], rmask);

        // ---- 6 hidden layers ----
#pragma unroll
        for (int l = 0; l < NLAYER; l++) {
            mma_layer(wfp + l * 1024, A, acc);
            if (l < NLAYER - 1) {
                epi_full(acc[0], rm[0][0], rm[0][1], bh0 + l * 64, cb, A[0], rmask);
                epi_full(acc[1], rm[1][0], rm[1][1], bh0 + l * 64, cb, A[1], rmask);
            } else {
                // output epilogue: dequant + bias + lrelu, dot wo, reduce, store
                const float* bl = bh0 + 5 * 64;
#pragma unroll
                for (int mt = 0; mt < 2; mt++) {
                    float r0v = rm[mt][0], r1v = rm[mt][1];
                    float d0 = 0.f, d1 = 0.f;
#pragma unroll
                    for (int nt = 0; nt < 8; nt++) {
                        float2 bv = *(const float2*)(bl + nt * 8 + cb);
                        float2 wv = *(const float2*)(shm_wo + nt * 8 + cb);
                        d0 = fmaf(lrelu(fmaf(acc[mt][nt][0], r0v, bv.x)), wv.x, d0);
                        d0 = fmaf(lrelu(fmaf(acc[mt][nt][1], r0v, bv.y)), wv.y, d0);
                        d1 = fmaf(lrelu(fmaf(acc[mt][nt][2], r1v, bv.x)), wv.x, d1);
                        d1 = fmaf(lrelu(fmaf(acc[mt][nt][3], r1v, bv.y)), wv.y, d1);
                    }
                    d0 += __shfl_xor_sync(0xffffffffu, d0, 1);
                    d0 += __shfl_xor_sync(0xffffffffu, d0, 2);
                    d1 += __shfl_xor_sync(0xffffffffu, d1, 1);
                    d1 += __shfl_xor_sync(0xffffffffu, d1, 2);
                    if (tig == 0) {
                        long long r0 = rowbase + mt * 16 + grp;
                        long long r1 = r0 + 8;
                        if (r0 < n) out[r0] = fmaf(d0, so_v, bo_v);
                        if (r1 < n) out[r1] = fmaf(d1, so_v, bo_v);
                    }
                }
            }
        }
    }
}

extern "C" void kernel_launch(void* const* d_in, const int* in_sizes, int n_in,
                              void* d_out, int out_size)
{
    const float* points = (const float*)d_in[0];
    const float* w0     = (const float*)d_in[1];
    const float* s0     = (const float*)d_in[2];
    const float* b0     = (const float*)d_in[3];
    const float* wh     = (const float*)d_in[4];
    const float* sh     = (const float*)d_in[5];
    const float* bh     = (const float*)d_in[6];
    const float* wo     = (const float*)d_in[7];
    const float* so     = (const float*)d_in[8];
    const float* bo     = (const float*)d_in[9];
    float* out = (float*)d_out;

    const int n = in_sizes[0] / 3;
    const int ntiles = (n + TILE_M - 1) / TILE_M;

    prep_weights<<<(NLAYER * 8 * 4 * 32 + 255) / 256, 256>>>(wh, sh);

    int sms = 148;
    cudaDeviceGetAttribute(&sms, cudaDevAttrMultiProcessorCount, 0);
    cudaFuncSetAttribute(implicit_mlp_f16,
                         cudaFuncAttributeMaxDynamicSharedMemorySize, SMEM_BYTES);
    int grid = sms < ntiles ? sms : ntiles;

    implicit_mlp_f16<<<grid, NT, SMEM_BYTES>>>(
        points, w0, s0, b0, bh, wo, so, bo, out, n, ntiles);
}